// round 3
// baseline (speedup 1.0000x reference)
#include <cuda_runtime.h>
#include <cuda_fp16.h>
#include <mma.h>

using namespace nvcuda;

// Problem dims
#define SQ 8192
#define DD 2048
#define HH 2048
#define H3 6144

// GRU persistent kernel config
#define NB  128      // blocks (all co-resident)
#define JPB 16       // hidden units per block
#define TPB 512      // threads per block (16 warps, warp w <-> hidden unit j0+w)

// GEMM config
#define BM 128
#define BN 128
#define BK 32
#define LDT 48       // smem row stride (halfs): multiple of 8, rows 96B => 32B aligned
#define NT (DD / BK) // 64 k-tiles

// -------- device scratch (no allocations allowed) --------
__device__ __half g_xh[(size_t)SQ * DD];    // x in fp16          (32 MB)
__device__ __half g_wih[(size_t)H3 * DD];   // W_ih in fp16       (25 MB)
__device__ float  g_xi[(size_t)SQ * H3];    // xi = x @ W_ih^T    (192 MB, fp32)
__device__ __half g_h[2][HH];               // double-buffered hidden state
__device__ unsigned g_sync;                 // grid-sync counter

// -------- init --------
__global__ void k_init() { g_sync = 0u; }

// -------- fp32 -> fp16 conversions --------
__global__ void k_cvt_x(const float2* __restrict__ src) {
    __half2* dst = (__half2*)g_xh;
    const int n = SQ * DD / 2;
    for (int i = blockIdx.x * blockDim.x + threadIdx.x; i < n; i += gridDim.x * blockDim.x)
        dst[i] = __float22half2_rn(src[i]);
}
__global__ void k_cvt_wih(const float2* __restrict__ src) {
    __half2* dst = (__half2*)g_wih;
    const int n = H3 * DD / 2;
    for (int i = blockIdx.x * blockDim.x + threadIdx.x; i < n; i += gridDim.x * blockDim.x)
        dst[i] = __float22half2_rn(src[i]);
}

// -------- xi GEMM: g_xi[s, r] = sum_k g_xh[s,k] * g_wih[r,k]  (bias added later) --------
__global__ __launch_bounds__(256)
void k_gemm() {
    extern __shared__ __half tsm[];
    __half* As = tsm;                     // [2][BM][LDT]
    __half* Bs = tsm + 2 * BM * LDT;      // [2][BN][LDT]

    const int tid = threadIdx.x;
    const int bm = blockIdx.y * BM;
    const int bn = blockIdx.x * BN;
    const int warp = tid >> 5;
    const int wm = (warp >> 1) * 32;      // warp tile: 32 x 64
    const int wn = (warp & 1) * 64;

    wmma::fragment<wmma::accumulator, 16, 16, 16, float> acc[2][4];
#pragma unroll
    for (int i = 0; i < 2; i++)
#pragma unroll
        for (int j = 0; j < 4; j++) wmma::fill_fragment(acc[i][j], 0.0f);

    const int r0 = tid >> 2;              // 0..63
    const int c0 = (tid & 3) * 8;         // 0,8,16,24

    const __half* A = g_xh + (size_t)(bm + r0) * DD + c0;
    const __half* B = g_wih + (size_t)(bn + r0) * DD + c0;

    uint4 pa0, pa1, pb0, pb1;
    // prologue: tile 0
    pa0 = *(const uint4*)(A);
    pa1 = *(const uint4*)(A + (size_t)64 * DD);
    pb0 = *(const uint4*)(B);
    pb1 = *(const uint4*)(B + (size_t)64 * DD);
    *(uint4*)&As[(0 * BM + r0) * LDT + c0]        = pa0;
    *(uint4*)&As[(0 * BM + r0 + 64) * LDT + c0]   = pa1;
    *(uint4*)&Bs[(0 * BN + r0) * LDT + c0]        = pb0;
    *(uint4*)&Bs[(0 * BN + r0 + 64) * LDT + c0]   = pb1;
    __syncthreads();

    for (int kt = 0; kt < NT; ++kt) {
        const int cur = kt & 1, nxt = cur ^ 1;
        if (kt + 1 < NT) {
            const int k0 = (kt + 1) * BK;
            pa0 = *(const uint4*)(A + k0);
            pa1 = *(const uint4*)(A + k0 + (size_t)64 * DD);
            pb0 = *(const uint4*)(B + k0);
            pb1 = *(const uint4*)(B + k0 + (size_t)64 * DD);
        }
#pragma unroll
        for (int kk = 0; kk < BK; kk += 16) {
            wmma::fragment<wmma::matrix_a, 16, 16, 16, __half, wmma::row_major> af[2];
            wmma::fragment<wmma::matrix_b, 16, 16, 16, __half, wmma::col_major> bf[4];
#pragma unroll
            for (int i = 0; i < 2; i++)
                wmma::load_matrix_sync(af[i], &As[(cur * BM + wm + i * 16) * LDT + kk], LDT);
#pragma unroll
            for (int j = 0; j < 4; j++)
                wmma::load_matrix_sync(bf[j], &Bs[(cur * BN + wn + j * 16) * LDT + kk], LDT);
#pragma unroll
            for (int i = 0; i < 2; i++)
#pragma unroll
                for (int j = 0; j < 4; j++)
                    wmma::mma_sync(acc[i][j], af[i], bf[j], acc[i][j]);
        }
        if (kt + 1 < NT) {
            *(uint4*)&As[(nxt * BM + r0) * LDT + c0]      = pa0;
            *(uint4*)&As[(nxt * BM + r0 + 64) * LDT + c0] = pa1;
            *(uint4*)&Bs[(nxt * BN + r0) * LDT + c0]      = pb0;
            *(uint4*)&Bs[(nxt * BN + r0 + 64) * LDT + c0] = pb1;
        }
        __syncthreads();
    }
#pragma unroll
    for (int i = 0; i < 2; i++)
#pragma unroll
        for (int j = 0; j < 4; j++)
            wmma::store_matrix_sync(&g_xi[(size_t)(bm + wm + i * 16) * H3 + bn + wn + j * 16],
                                    acc[i][j], H3, wmma::mem_row_major);
}

// -------- persistent GRU recurrence --------
// Block b owns hidden units j0..j0+15 (j0 = b*16). Warp w handles j = j0+w.
// SMEM holds the block's 48 W_hh rows (fp16) for the entire run + 4KB h staging.
#define GRU_SMEM (48 * 2048 * 2 + 2048 * 2)

__global__ __launch_bounds__(TPB, 1)
void k_gru(const float* __restrict__ Whh, const float* __restrict__ bih,
           const float* __restrict__ bhh, float* __restrict__ out) {
    extern __shared__ char smem[];
    __half* wsm = (__half*)smem;                       // [48][2048]
    __half* hsm = (__half*)(smem + 48 * 2048 * 2);     // [2048]

    const int tid = threadIdx.x;
    const int w = tid >> 5, l = tid & 31;
    const int j0 = blockIdx.x * JPB;
    const int j = j0 + w;

    // Load + convert this block's 48 weight rows into smem.
    // smem row r = 3*jj + g  <->  global row g*HH + j0 + jj  (g: 0=r,1=z,2=n)
    for (int idx = tid; idx < 48 * 2048; idx += TPB) {
        const int r = idx >> 11, c = idx & 2047;
        const int g = r % 3, jj = r / 3;
        wsm[idx] = __float2half(Whh[(size_t)(g * HH + j0 + jj) * HH + c]);
    }
    const float br = bhh[j], bz = bhh[HH + j], bn = bhh[2 * HH + j];
    const float cr = bih[j], cz = bih[HH + j], cn = bih[2 * HH + j];
    __syncthreads();

    const uint4* hv = (const uint4*)hsm;
    const uint4* w0 = (const uint4*)(wsm + (3 * w + 0) * 2048);
    const uint4* w1 = (const uint4*)(wsm + (3 * w + 1) * 2048);
    const uint4* w2 = (const uint4*)(wsm + (3 * w + 2) * 2048);

    float hown = 0.f;

#pragma unroll 1
    for (int t = 0; t < SQ; ++t) {
        // xi for this step (issued early; ready long before use)
        const float* xt = g_xi + (size_t)t * H3;
        const float xr = xt[j], xz = xt[HH + j], xn = xt[2 * HH + j];

        float hr, hz, hn;
        if (t == 0) {
            hr = hz = hn = 0.f;   // h_{-1} = 0
        } else {
            // wait for all blocks to finish step t-1
            if (tid == 0) {
                const unsigned target = (unsigned)t * NB;
                while (*(volatile unsigned*)&g_sync < target) {}
                __threadfence();
            }
            __syncthreads();
            // stage h_{t-1} into smem (L2-fresh loads; L1 may be stale)
            ((uint2*)hsm)[tid] = __ldcg(((const uint2*)g_h[(t - 1) & 1]) + tid);
            __syncthreads();

            // GEMV: 3 rows x 2048, fp16 data, fp32 accumulate
            float2 a0 = {0.f, 0.f}, a1 = {0.f, 0.f}, a2 = {0.f, 0.f};
#pragma unroll
            for (int c = 0; c < 8; ++c) {
                const int o = c * 32 + l;
                const uint4 hq = hv[o];
                const uint4 q0 = w0[o];
                const uint4 q1 = w1[o];
                const uint4 q2 = w2[o];
                float2 hf0 = __half22float2(*(const __half2*)&hq.x);
                float2 hf1 = __half22float2(*(const __half2*)&hq.y);
                float2 hf2 = __half22float2(*(const __half2*)&hq.z);
                float2 hf3 = __half22float2(*(const __half2*)&hq.w);
                float2 f;
                f = __half22float2(*(const __half2*)&q0.x); a0.x = fmaf(f.x, hf0.x, a0.x); a0.y = fmaf(f.y, hf0.y, a0.y);
                f = __half22float2(*(const __half2*)&q0.y); a0.x = fmaf(f.x, hf1.x, a0.x); a0.y = fmaf(f.y, hf1.y, a0.y);
                f = __half22float2(*(const __half2*)&q0.z); a0.x = fmaf(f.x, hf2.x, a0.x); a0.y = fmaf(f.y, hf2.y, a0.y);
                f = __half22float2(*(const __half2*)&q0.w); a0.x = fmaf(f.x, hf3.x, a0.x); a0.y = fmaf(f.y, hf3.y, a0.y);
                f = __half22float2(*(const __half2*)&q1.x); a1.x = fmaf(f.x, hf0.x, a1.x); a1.y = fmaf(f.y, hf0.y, a1.y);
                f = __half22float2(*(const __half2*)&q1.y); a1.x = fmaf(f.x, hf1.x, a1.x); a1.y = fmaf(f.y, hf1.y, a1.y);
                f = __half22float2(*(const __half2*)&q1.z); a1.x = fmaf(f.x, hf2.x, a1.x); a1.y = fmaf(f.y, hf2.y, a1.y);
                f = __half22float2(*(const __half2*)&q1.w); a1.x = fmaf(f.x, hf3.x, a1.x); a1.y = fmaf(f.y, hf3.y, a1.y);
                f = __half22float2(*(const __half2*)&q2.x); a2.x = fmaf(f.x, hf0.x, a2.x); a2.y = fmaf(f.y, hf0.y, a2.y);
                f = __half22float2(*(const __half2*)&q2.y); a2.x = fmaf(f.x, hf1.x, a2.x); a2.y = fmaf(f.y, hf1.y, a2.y);
                f = __half22float2(*(const __half2*)&q2.z); a2.x = fmaf(f.x, hf2.x, a2.x); a2.y = fmaf(f.y, hf2.y, a2.y);
                f = __half22float2(*(const __half2*)&q2.w); a2.x = fmaf(f.x, hf3.x, a2.x); a2.y = fmaf(f.y, hf3.y, a2.y);
            }
            float s0 = a0.x + a0.y, s1 = a1.x + a1.y, s2 = a2.x + a2.y;
#pragma unroll
            for (int off = 16; off > 0; off >>= 1) {
                s0 += __shfl_xor_sync(0xffffffffu, s0, off);
                s1 += __shfl_xor_sync(0xffffffffu, s1, off);
                s2 += __shfl_xor_sync(0xffffffffu, s2, off);
            }
            hr = s0; hz = s1; hn = s2;
        }

        // gates (all lanes compute identically; lane 0 stores)
        const float rg = 1.f / (1.f + __expf(-(xr + cr + hr + br)));
        const float zg = 1.f / (1.f + __expf(-(xz + cz + hz + bz)));
        const float ng = tanhf(xn + cn + rg * (hn + bn));
        const float hnew = (1.f - zg) * ng + zg * hown;
        hown = hnew;
        if (l == 0) g_h[t & 1][j] = __float2half(hnew);

        __syncthreads();
        if (tid == 0) { __threadfence(); atomicAdd(&g_sync, 1u); }
    }

    if (l == 0) out[j] = hown;
}

// -------- launcher --------
extern "C" void kernel_launch(void* const* d_in, const int* in_sizes, int n_in,
                              void* d_out, int out_size) {
    const float* x   = (const float*)d_in[0];
    // d_in[1] = W_ih, d_in[2] = W_hh, d_in[3] = b_ih, d_in[4] = b_hh
    const float* Wih = (const float*)d_in[1];
    const float* Whh = (const float*)d_in[2];
    const float* bih = (const float*)d_in[3];
    const float* bhh = (const float*)d_in[4];
    float* out = (float*)d_out;

    k_init<<<1, 1>>>();
    k_cvt_x<<<2048, 256>>>((const float2*)x);
    k_cvt_wih<<<2048, 256>>>((const float2*)Wih);

    const int gemm_smem = 2 * (BM + BN) * LDT * (int)sizeof(__half); // 49152
    cudaFuncSetAttribute(k_gemm, cudaFuncAttributeMaxDynamicSharedMemorySize, gemm_smem);
    dim3 ggrid(H3 / BN, SQ / BM);
    k_gemm<<<ggrid, 256, gemm_smem>>>();

    cudaFuncSetAttribute(k_gru, cudaFuncAttributeMaxDynamicSharedMemorySize, GRU_SMEM);
    k_gru<<<NB, TPB, GRU_SMEM>>>(Whh, bih, bhh, out);
}